// round 2
// baseline (speedup 1.0000x reference)
#include <cuda_runtime.h>
#include <math.h>

#define B_    2
#define S_    8192
#define DM    512
#define H_    8
#define D_    64
#define W_    128
#define DH    2048
#define NT    (B_ * S_)            // 16384 tokens
#define BAND  257                  // 2*W+1
#define QC    256                  // queries per attention block
#define KW    (QC + 2 * W_)        // 512 key rows per window
#define KPAD  65                   // padded row stride in smem (floats)

// ---------------- scratch (device globals; no allocation allowed) ----------
__device__ float g_q[B_ * H_ * S_ * D_];
__device__ float g_k[B_ * H_ * S_ * D_];
__device__ float g_v[B_ * H_ * S_ * D_];
__device__ float g_attn[NT * DM];   // attention out; later reused for FFN2 out
__device__ float g_h[NT * DM];      // after LN1
__device__ float g_ff[NT * DH];     // FFN hidden

// ---------------- generic fp32 SGEMM: C = A(MxK) @ B(KxN) + bias ----------
// MODE 0: plain (+bias), MODE 1: relu(+bias), MODE 2: QKV head-split layout,
//         value scaled by `scale` after bias.
template <int MODE>
__global__ void __launch_bounds__(256) sgemm_kernel(
    const float* __restrict__ A, const float* __restrict__ Bw,
    const float* __restrict__ bias, float* __restrict__ C,
    int N, int K, float scale)
{
    __shared__ float As[8][128];
    __shared__ float Bs[8][128];

    const int tid  = threadIdx.x;
    const int row0 = blockIdx.y * 128;
    const int col0 = blockIdx.x * 128;
    const int tx = tid & 15;
    const int ty = tid >> 4;

    const int arow = tid >> 1;
    const int acol = (tid & 1) * 4;
    const int brow = tid >> 5;
    const int bcol = (tid & 31) * 4;

    const float* Aptr = A + (size_t)(row0 + arow) * K + acol;
    const float* Bptr = Bw + (size_t)brow * N + col0 + bcol;

    float acc[8][8];
#pragma unroll
    for (int i = 0; i < 8; i++)
#pragma unroll
        for (int j = 0; j < 8; j++) acc[i][j] = 0.0f;

    for (int kt = 0; kt < K; kt += 8) {
        float4 av = *(const float4*)Aptr;  Aptr += 8;
        float4 bv = *(const float4*)Bptr;  Bptr += (size_t)8 * N;

        __syncthreads();   // prev compute done before overwriting smem
        As[acol + 0][arow] = av.x;
        As[acol + 1][arow] = av.y;
        As[acol + 2][arow] = av.z;
        As[acol + 3][arow] = av.w;
        *(float4*)&Bs[brow][bcol] = bv;
        __syncthreads();

#pragma unroll
        for (int k = 0; k < 8; k++) {
            float a[8], b[8];
#pragma unroll
            for (int i = 0; i < 8; i++) a[i] = As[k][ty * 8 + i];
#pragma unroll
            for (int j = 0; j < 8; j++) b[j] = Bs[k][tx * 8 + j];
#pragma unroll
            for (int i = 0; i < 8; i++)
#pragma unroll
                for (int j = 0; j < 8; j++)
                    acc[i][j] = fmaf(a[i], b[j], acc[i][j]);
        }
    }

#pragma unroll
    for (int i = 0; i < 8; i++) {
        const int r = row0 + ty * 8 + i;
#pragma unroll
        for (int j = 0; j < 8; j++) {
            const int c = col0 + tx * 8 + j;
            float v = acc[i][j] + bias[c];
            if (MODE == 1) v = fmaxf(v, 0.0f);
            if (MODE == 2) {
                v *= scale;
                const int b  = r >> 13;        // token / S
                const int s  = r & (S_ - 1);
                const int h  = c >> 6;         // col / D
                const int d  = c & 63;
                C[((size_t)(b * H_ + h) * S_ + s) * D_ + d] = v;
            } else {
                C[(size_t)r * N + c] = v;
            }
        }
    }
}

// ---------------- attention: scores + softmax -> probs (the score output) --
__global__ void __launch_bounds__(256) attn_scores_kernel(
    const float* __restrict__ q, const float* __restrict__ k,
    float* __restrict__ score)
{
    extern __shared__ float ksm[];              // KW x KPAD
    const int bh  = blockIdx.y;
    const int q0  = blockIdx.x * QC;
    const int tid = threadIdx.x;

    const float* kb = k + (size_t)bh * S_ * D_;

    // stage K window [q0-W, q0+QC+W)
    for (int idx = tid; idx < KW * (D_ / 4); idx += 256) {
        const int row = idx >> 4;               // 16 float4 per row
        const int c4  = (idx & 15) * 4;
        const int kpos = q0 - W_ + row;
        float4 v = make_float4(0.f, 0.f, 0.f, 0.f);
        if (kpos >= 0 && kpos < S_)
            v = *(const float4*)(kb + (size_t)kpos * D_ + c4);
        float* dst = ksm + row * KPAD + c4;
        dst[0] = v.x; dst[1] = v.y; dst[2] = v.z; dst[3] = v.w;
    }
    __syncthreads();

    const int qi = q0 + tid;
    const float* qp = q + ((size_t)bh * S_ + qi) * D_;
    float qr[64];
#pragma unroll
    for (int i = 0; i < 16; i++) {
        float4 v = *(const float4*)(qp + i * 4);
        qr[i * 4 + 0] = v.x; qr[i * 4 + 1] = v.y;
        qr[i * 4 + 2] = v.z; qr[i * 4 + 3] = v.w;
    }

    float sc[BAND];
    float m = -1e30f;
#pragma unroll 1
    for (int j = 0; j < BAND; j++) {
        const int kpos = qi - W_ + j;
        const float* kr = ksm + (tid + j) * KPAD;
        float d0 = 0.f;
#pragma unroll
        for (int d = 0; d < 64; d++) d0 = fmaf(qr[d], kr[d], d0);
        // out-of-sequence keys were staged as zero rows; force them to -inf-ish
        const float dot = (kpos >= 0 && kpos < S_) ? d0 : -1e30f;
        sc[j] = dot;
        m = fmaxf(m, dot);
    }

    float sum = 0.f;
#pragma unroll 1
    for (int j = 0; j < BAND; j++) {
        const float e = expf(sc[j] - m);        // masked -> exp(-1e30)=0
        sc[j] = e;
        sum += e;
    }
    const float inv = 1.0f / sum;

    float* so = score + ((size_t)bh * S_ + qi) * BAND;
#pragma unroll 1
    for (int j = 0; j < BAND; j++) so[j] = sc[j] * inv;
}

// ---------------- attention: out = probs @ V ------------------------------
__global__ void __launch_bounds__(256) attn_pv_kernel(
    const float* __restrict__ v, const float* __restrict__ score,
    float* __restrict__ attn)
{
    extern __shared__ float vsm[];              // KW x KPAD
    const int bh  = blockIdx.y;
    const int q0  = blockIdx.x * QC;
    const int tid = threadIdx.x;

    const float* vb = v + (size_t)bh * S_ * D_;
    for (int idx = tid; idx < KW * (D_ / 4); idx += 256) {
        const int row = idx >> 4;
        const int c4  = (idx & 15) * 4;
        const int kpos = q0 - W_ + row;
        float4 val = make_float4(0.f, 0.f, 0.f, 0.f);
        if (kpos >= 0 && kpos < S_)
            val = *(const float4*)(vb + (size_t)kpos * D_ + c4);
        float* dst = vsm + row * KPAD + c4;
        dst[0] = val.x; dst[1] = val.y; dst[2] = val.z; dst[3] = val.w;
    }
    __syncthreads();

    const int qi = q0 + tid;
    const float* sp = score + ((size_t)bh * S_ + qi) * BAND;

    float acc[64];
#pragma unroll
    for (int d = 0; d < 64; d++) acc[d] = 0.f;

#pragma unroll 1
    for (int j = 0; j < BAND; j++) {
        const float p = sp[j];                  // 0 at masked positions
        const float* vr = vsm + (tid + j) * KPAD;
#pragma unroll
        for (int d = 0; d < 64; d++) acc[d] = fmaf(p, vr[d], acc[d]);
    }

    const int b = bh >> 3;
    const int h = bh & 7;
    float* op = attn + ((size_t)b * S_ + qi) * DM + h * D_;
#pragma unroll
    for (int i = 0; i < 16; i++) {
        float4 o;
        o.x = acc[i * 4 + 0]; o.y = acc[i * 4 + 1];
        o.z = acc[i * 4 + 2]; o.w = acc[i * 4 + 3];
        *(float4*)(op + i * 4) = o;
    }
}

// ---------------- fused residual + LayerNorm ------------------------------
__global__ void __launch_bounds__(128) ln_kernel(
    const float* __restrict__ a, const float* __restrict__ b,
    const float* __restrict__ gw, const float* __restrict__ bw,
    float* __restrict__ out)
{
    const int t   = blockIdx.x;
    const int tid = threadIdx.x;                // 128 threads x 4 elems

    const float4 xa = ((const float4*)(a + (size_t)t * DM))[tid];
    const float4 xb = ((const float4*)(b + (size_t)t * DM))[tid];
    const float v0 = xa.x + xb.x, v1 = xa.y + xb.y;
    const float v2 = xa.z + xb.z, v3 = xa.w + xb.w;

    float s  = v0 + v1 + v2 + v3;
    float ss = v0 * v0 + v1 * v1 + v2 * v2 + v3 * v3;
#pragma unroll
    for (int o = 16; o > 0; o >>= 1) {
        s  += __shfl_xor_sync(0xffffffffu, s,  o);
        ss += __shfl_xor_sync(0xffffffffu, ss, o);
    }
    __shared__ float sm[8];
    const int w = tid >> 5;
    if ((tid & 31) == 0) { sm[w] = s; sm[4 + w] = ss; }
    __syncthreads();
    s  = sm[0] + sm[1] + sm[2] + sm[3];
    ss = sm[4] + sm[5] + sm[6] + sm[7];

    const float mu  = s * (1.0f / DM);
    const float var = ss * (1.0f / DM) - mu * mu;
    const float r   = rsqrtf(var + 1e-5f);

    const float4 g4 = ((const float4*)gw)[tid];
    const float4 b4 = ((const float4*)bw)[tid];
    float4 o4;
    o4.x = (v0 - mu) * r * g4.x + b4.x;
    o4.y = (v1 - mu) * r * g4.y + b4.y;
    o4.z = (v2 - mu) * r * g4.z + b4.z;
    o4.w = (v3 - mu) * r * g4.w + b4.w;
    ((float4*)(out + (size_t)t * DM))[tid] = o4;
}

// ---------------- launch --------------------------------------------------
extern "C" void kernel_launch(void* const* d_in, const int* in_sizes, int n_in,
                              void* d_out, int out_size)
{
    const float* x    = (const float*)d_in[0];
    const float* Wq   = (const float*)d_in[1];
    const float* bq   = (const float*)d_in[2];
    const float* Wk   = (const float*)d_in[3];
    const float* bk   = (const float*)d_in[4];
    const float* Wv   = (const float*)d_in[5];
    const float* bv   = (const float*)d_in[6];
    const float* ln1g = (const float*)d_in[7];
    const float* ln1b = (const float*)d_in[8];
    const float* Wf1  = (const float*)d_in[9];
    const float* bf1  = (const float*)d_in[10];
    const float* Wf2  = (const float*)d_in[11];
    const float* bf2  = (const float*)d_in[12];
    const float* ln2g = (const float*)d_in[13];
    const float* ln2b = (const float*)d_in[14];

    float* out   = (float*)d_out;               // (B, S, DM)
    float* score = out + (size_t)NT * DM;       // (B, H, S, 257)

    float *q, *k, *v, *attn, *h, *ff;
    cudaGetSymbolAddress((void**)&q,    g_q);
    cudaGetSymbolAddress((void**)&k,    g_k);
    cudaGetSymbolAddress((void**)&v,    g_v);
    cudaGetSymbolAddress((void**)&attn, g_attn);
    cudaGetSymbolAddress((void**)&h,    g_h);
    cudaGetSymbolAddress((void**)&ff,   g_ff);

    const size_t attn_smem = (size_t)KW * KPAD * sizeof(float);  // 133120 B
    cudaFuncSetAttribute(attn_scores_kernel,
                         cudaFuncAttributeMaxDynamicSharedMemorySize, attn_smem);
    cudaFuncSetAttribute(attn_pv_kernel,
                         cudaFuncAttributeMaxDynamicSharedMemorySize, attn_smem);

    // QKV projections (head-split layout, q pre-scaled by 1/sqrt(D))
    dim3 gqkv(DM / 128, NT / 128);
    sgemm_kernel<2><<<gqkv, 256>>>(x, Wq, bq, q, DM, DM, 0.125f);
    sgemm_kernel<2><<<gqkv, 256>>>(x, Wk, bk, k, DM, DM, 1.0f);
    sgemm_kernel<2><<<gqkv, 256>>>(x, Wv, bv, v, DM, DM, 1.0f);

    // sliding-window attention
    dim3 gattn(S_ / QC, B_ * H_);
    attn_scores_kernel<<<gattn, 256, attn_smem>>>(q, k, score);
    attn_pv_kernel<<<gattn, 256, attn_smem>>>(v, score, attn);

    // h = LN1(attn + x)
    ln_kernel<<<NT, 128>>>(attn, x, ln1g, ln1b, h);

    // FFN
    dim3 gf1(DH / 128, NT / 128);
    sgemm_kernel<1><<<gf1, 256>>>(h, Wf1, bf1, ff, DH, DM, 1.0f);
    dim3 gf2(DM / 128, NT / 128);
    sgemm_kernel<0><<<gf2, 256>>>(ff, Wf2, bf2, attn, DM, DH, 1.0f);  // reuse attn buf

    // out = LN2(ff2 + h)
    ln_kernel<<<NT, 128>>>(attn, h, ln2g, ln2b, out);
}

// round 4
// speedup vs baseline: 1.4992x; 1.4992x over previous
#include <cuda_runtime.h>
#include <math.h>
#include <stdint.h>

#define B_    2
#define S_    8192
#define DM    512
#define H_    8
#define D_    64
#define W_    128
#define DH    2048
#define NT    (B_ * S_)            // 16384 tokens
#define BAND  257                  // 2*W+1
#define QC    256                  // queries per attention block
#define KW    (QC + 2 * W_)        // 512 key rows per window
#define KPAD  65                   // padded row stride in smem (floats)

// ---------------- scratch (device globals; no allocation allowed) ----------
__device__ float g_q[B_ * H_ * S_ * D_];
__device__ float g_k[B_ * H_ * S_ * D_];
__device__ float g_v[B_ * H_ * S_ * D_];
__device__ float g_attn[NT * DM];   // attention out; later reused for FFN2 out
__device__ float g_h[NT * DM];      // after LN1
__device__ float g_ff[NT * DH];     // FFN hidden

// ---------------- tf32 helpers --------------------------------------------
__device__ __forceinline__ uint32_t f2tf32(float x) {
    uint32_t r;
    asm("cvt.rna.tf32.f32 %0, %1;" : "=r"(r) : "f"(x));
    return r;
}

__device__ __forceinline__ void mma_tf32(float c[4],
    uint32_t a0, uint32_t a1, uint32_t a2, uint32_t a3,
    uint32_t b0, uint32_t b1)
{
    asm volatile(
        "mma.sync.aligned.m16n8k8.row.col.f32.tf32.tf32.f32 "
        "{%0,%1,%2,%3}, {%4,%5,%6,%7}, {%8,%9}, {%0,%1,%2,%3};"
        : "+f"(c[0]), "+f"(c[1]), "+f"(c[2]), "+f"(c[3])
        : "r"(a0), "r"(a1), "r"(a2), "r"(a3), "r"(b0), "r"(b1));
}

// ---------------- tf32 tensor-core GEMM: C = A(MxK) @ B(KxN) + bias -------
// MODE 0: plain (+bias), MODE 1: relu(+bias), MODE 2: QKV head-split layout,
//         value scaled by `scale` after bias.
// Tiles: 128x128xBK16; 8 warps, each 64x32 (4x4 atoms of m16n8k8).
#define ASTRIDE 20
#define BSTRIDE 136

template <int MODE>
__global__ void __launch_bounds__(256) tgemm_kernel(
    const float* __restrict__ A, const float* __restrict__ Bw,
    const float* __restrict__ bias, float* __restrict__ C,
    int N, int K, float scale)
{
    __shared__ uint32_t As[128 * ASTRIDE];   // [m][k] tf32 bits
    __shared__ uint32_t Bs[16 * BSTRIDE];    // [k][n] tf32 bits

    const int tid  = threadIdx.x;
    const int wid  = tid >> 5;
    const int lane = tid & 31;
    const int g    = lane >> 2;              // 0..7
    const int t    = lane & 3;               // 0..3

    const int row0 = blockIdx.y * 128;
    const int col0 = blockIdx.x * 128;
    const int wm   = (wid & 1) * 64;         // warp m offset
    const int wn   = (wid >> 1) * 32;        // warp n offset

    // global load indices
    const int a_row  = tid >> 1;             // 0..127
    const int a_col  = (tid & 1) * 8;        // 0 or 8
    const int b_row  = tid >> 4;             // 0..15
    const int b_col  = (tid & 15) * 8;       // 0..120

    const float* Aptr = A + (size_t)(row0 + a_row) * K + a_col;
    const float* Bptr = Bw + (size_t)b_row * N + col0 + b_col;

    float acc[4][4][4];
#pragma unroll
    for (int i = 0; i < 4; i++)
#pragma unroll
        for (int j = 0; j < 4; j++)
#pragma unroll
            for (int r = 0; r < 4; r++) acc[i][j][r] = 0.0f;

    for (int k0 = 0; k0 < K; k0 += 16) {
        float4 av0 = *(const float4*)(Aptr + 0);
        float4 av1 = *(const float4*)(Aptr + 4);
        float4 bv0 = *(const float4*)(Bptr + 0);
        float4 bv1 = *(const float4*)(Bptr + 4);
        Aptr += 16;
        Bptr += (size_t)16 * N;

        __syncthreads();   // previous compute done before smem overwrite
        uint32_t* adst = &As[a_row * ASTRIDE + a_col];
        adst[0] = f2tf32(av0.x); adst[1] = f2tf32(av0.y);
        adst[2] = f2tf32(av0.z); adst[3] = f2tf32(av0.w);
        adst[4] = f2tf32(av1.x); adst[5] = f2tf32(av1.y);
        adst[6] = f2tf32(av1.z); adst[7] = f2tf32(av1.w);
        uint32_t* bdst = &Bs[b_row * BSTRIDE + b_col];
        bdst[0] = f2tf32(bv0.x); bdst[1] = f2tf32(bv0.y);
        bdst[2] = f2tf32(bv0.z); bdst[3] = f2tf32(bv0.w);
        bdst[4] = f2tf32(bv1.x); bdst[5] = f2tf32(bv1.y);
        bdst[6] = f2tf32(bv1.z); bdst[7] = f2tf32(bv1.w);
        __syncthreads();

#pragma unroll
        for (int ks = 0; ks < 16; ks += 8) {
            uint32_t afr[4][4];
#pragma unroll
            for (int ma = 0; ma < 4; ma++) {
                const int m = wm + ma * 16 + g;
                afr[ma][0] = As[(m + 0) * ASTRIDE + ks + t];
                afr[ma][1] = As[(m + 8) * ASTRIDE + ks + t];
                afr[ma][2] = As[(m + 0) * ASTRIDE + ks + t + 4];
                afr[ma][3] = As[(m + 8) * ASTRIDE + ks + t + 4];
            }
            uint32_t bfr[4][2];
#pragma unroll
            for (int na = 0; na < 4; na++) {
                const int n = wn + na * 8 + g;
                bfr[na][0] = Bs[(ks + t + 0) * BSTRIDE + n];
                bfr[na][1] = Bs[(ks + t + 4) * BSTRIDE + n];
            }
#pragma unroll
            for (int ma = 0; ma < 4; ma++)
#pragma unroll
                for (int na = 0; na < 4; na++)
                    mma_tf32(acc[ma][na],
                             afr[ma][0], afr[ma][1], afr[ma][2], afr[ma][3],
                             bfr[na][0], bfr[na][1]);
        }
    }

    // epilogue: thread owns (g row, t*2 col) pairs per atom
#pragma unroll
    for (int ma = 0; ma < 4; ma++) {
#pragma unroll
        for (int na = 0; na < 4; na++) {
#pragma unroll
            for (int half = 0; half < 2; half++) {     // c0/c1 vs c2/c3
                const int r = row0 + wm + ma * 16 + g + half * 8;
                const int c = col0 + wn + na * 8 + t * 2;
                float v0 = acc[ma][na][half * 2 + 0] + bias[c + 0];
                float v1 = acc[ma][na][half * 2 + 1] + bias[c + 1];
                if (MODE == 1) { v0 = fmaxf(v0, 0.f); v1 = fmaxf(v1, 0.f); }
                if (MODE == 2) {
                    v0 *= scale; v1 *= scale;
                    const int b = r >> 13;            // token / S
                    const int s = r & (S_ - 1);
                    const int h = c >> 6;             // col / D
                    const int d = c & 63;
                    float2 o; o.x = v0; o.y = v1;
                    *(float2*)&C[((size_t)(b * H_ + h) * S_ + s) * D_ + d] = o;
                } else {
                    float2 o; o.x = v0; o.y = v1;
                    *(float2*)&C[(size_t)r * N + c] = o;
                }
            }
        }
    }
}

// ---------------- attention: scores + online softmax -> probs -------------
__global__ void __launch_bounds__(256) attn_scores_kernel(
    const float* __restrict__ q, const float* __restrict__ k,
    float* __restrict__ score)
{
    extern __shared__ float ksm[];              // KW x KPAD
    const int bh  = blockIdx.y;
    const int q0  = blockIdx.x * QC;
    const int tid = threadIdx.x;

    const float* kb = k + (size_t)bh * S_ * D_;

    // stage K window [q0-W, q0+QC+W)
    for (int idx = tid; idx < KW * (D_ / 4); idx += 256) {
        const int row = idx >> 4;               // 16 float4 per row
        const int c4  = (idx & 15) * 4;
        const int kpos = q0 - W_ + row;
        float4 v = make_float4(0.f, 0.f, 0.f, 0.f);
        if (kpos >= 0 && kpos < S_)
            v = *(const float4*)(kb + (size_t)kpos * D_ + c4);
        float* dst = ksm + row * KPAD + c4;
        dst[0] = v.x; dst[1] = v.y; dst[2] = v.z; dst[3] = v.w;
    }
    __syncthreads();

    const int qi = q0 + tid;
    const float* qp = q + ((size_t)bh * S_ + qi) * D_;
    float qr[64];
#pragma unroll
    for (int i = 0; i < 16; i++) {
        float4 v = *(const float4*)(qp + i * 4);
        qr[i * 4 + 0] = v.x; qr[i * 4 + 1] = v.y;
        qr[i * 4 + 2] = v.z; qr[i * 4 + 3] = v.w;
    }

    // pass 1: online max + sum (no per-band storage)
    float m = -1e30f, sum = 0.f;
#pragma unroll 1
    for (int j = 0; j < BAND; j++) {
        const int kpos = qi - W_ + j;
        const float* kr = ksm + (tid + j) * KPAD;
        float d0 = 0.f;
#pragma unroll
        for (int d = 0; d < 64; d++) d0 = fmaf(qr[d], kr[d], d0);
        const float dot = (kpos >= 0 && kpos < S_) ? d0 : -1e30f;
        const float mn = fmaxf(m, dot);
        sum = sum * __expf(m - mn) + __expf(dot - mn);
        m = mn;
    }
    const float inv = 1.0f / sum;

    // pass 2: recompute dots, write normalized probs
    float* so = score + ((size_t)bh * S_ + qi) * BAND;
#pragma unroll 1
    for (int j = 0; j < BAND; j++) {
        const int kpos = qi - W_ + j;
        const float* kr = ksm + (tid + j) * KPAD;
        float d0 = 0.f;
#pragma unroll
        for (int d = 0; d < 64; d++) d0 = fmaf(qr[d], kr[d], d0);
        const float dot = (kpos >= 0 && kpos < S_) ? d0 : -1e30f;
        so[j] = __expf(dot - m) * inv;
    }
}

// ---------------- attention: out = probs @ V ------------------------------
__global__ void __launch_bounds__(256) attn_pv_kernel(
    const float* __restrict__ v, const float* __restrict__ score,
    float* __restrict__ attn)
{
    extern __shared__ float vsm[];              // KW x KPAD
    const int bh  = blockIdx.y;
    const int q0  = blockIdx.x * QC;
    const int tid = threadIdx.x;

    const float* vb = v + (size_t)bh * S_ * D_;
    for (int idx = tid; idx < KW * (D_ / 4); idx += 256) {
        const int row = idx >> 4;
        const int c4  = (idx & 15) * 4;
        const int kpos = q0 - W_ + row;
        float4 val = make_float4(0.f, 0.f, 0.f, 0.f);
        if (kpos >= 0 && kpos < S_)
            val = *(const float4*)(vb + (size_t)kpos * D_ + c4);
        float* dst = vsm + row * KPAD + c4;
        dst[0] = val.x; dst[1] = val.y; dst[2] = val.z; dst[3] = val.w;
    }
    __syncthreads();

    const int qi = q0 + tid;
    const float* sp = score + ((size_t)bh * S_ + qi) * BAND;

    float acc[64];
#pragma unroll
    for (int d = 0; d < 64; d++) acc[d] = 0.f;

#pragma unroll 1
    for (int j = 0; j < BAND; j++) {
        const float p = sp[j];                  // 0 at masked positions
        const float* vr = vsm + (tid + j) * KPAD;
#pragma unroll
        for (int d = 0; d < 64; d++) acc[d] = fmaf(p, vr[d], acc[d]);
    }

    const int b = bh >> 3;
    const int h = bh & 7;
    float* op = attn + ((size_t)b * S_ + qi) * DM + h * D_;
#pragma unroll
    for (int i = 0; i < 16; i++) {
        float4 o;
        o.x = acc[i * 4 + 0]; o.y = acc[i * 4 + 1];
        o.z = acc[i * 4 + 2]; o.w = acc[i * 4 + 3];
        *(float4*)(op + i * 4) = o;
    }
}

// ---------------- fused residual + LayerNorm ------------------------------
__global__ void __launch_bounds__(128) ln_kernel(
    const float* __restrict__ a, const float* __restrict__ b,
    const float* __restrict__ gw, const float* __restrict__ bw,
    float* __restrict__ out)
{
    const int t   = blockIdx.x;
    const int tid = threadIdx.x;                // 128 threads x 4 elems

    const float4 xa = ((const float4*)(a + (size_t)t * DM))[tid];
    const float4 xb = ((const float4*)(b + (size_t)t * DM))[tid];
    const float v0 = xa.x + xb.x, v1 = xa.y + xb.y;
    const float v2 = xa.z + xb.z, v3 = xa.w + xb.w;

    float s  = v0 + v1 + v2 + v3;
    float ss = v0 * v0 + v1 * v1 + v2 * v2 + v3 * v3;
#pragma unroll
    for (int o = 16; o > 0; o >>= 1) {
        s  += __shfl_xor_sync(0xffffffffu, s,  o);
        ss += __shfl_xor_sync(0xffffffffu, ss, o);
    }
    __shared__ float sm[8];
    const int w = tid >> 5;
    if ((tid & 31) == 0) { sm[w] = s; sm[4 + w] = ss; }
    __syncthreads();
    s  = sm[0] + sm[1] + sm[2] + sm[3];
    ss = sm[4] + sm[5] + sm[6] + sm[7];

    const float mu  = s * (1.0f / DM);
    const float var = ss * (1.0f / DM) - mu * mu;
    const float r   = rsqrtf(var + 1e-5f);

    const float4 g4 = ((const float4*)gw)[tid];
    const float4 b4 = ((const float4*)bw)[tid];
    float4 o4;
    o4.x = (v0 - mu) * r * g4.x + b4.x;
    o4.y = (v1 - mu) * r * g4.y + b4.y;
    o4.z = (v2 - mu) * r * g4.z + b4.z;
    o4.w = (v3 - mu) * r * g4.w + b4.w;
    ((float4*)(out + (size_t)t * DM))[tid] = o4;
}

// ---------------- launch --------------------------------------------------
extern "C" void kernel_launch(void* const* d_in, const int* in_sizes, int n_in,
                              void* d_out, int out_size)
{
    const float* x    = (const float*)d_in[0];
    const float* Wq   = (const float*)d_in[1];
    const float* bq   = (const float*)d_in[2];
    const float* Wk   = (const float*)d_in[3];
    const float* bk   = (const float*)d_in[4];
    const float* Wv   = (const float*)d_in[5];
    const float* bv   = (const float*)d_in[6];
    const float* ln1g = (const float*)d_in[7];
    const float* ln1b = (const float*)d_in[8];
    const float* Wf1  = (const float*)d_in[9];
    const float* bf1  = (const float*)d_in[10];
    const float* Wf2  = (const float*)d_in[11];
    const float* bf2  = (const float*)d_in[12];
    const float* ln2g = (const float*)d_in[13];
    const float* ln2b = (const float*)d_in[14];

    float* out   = (float*)d_out;               // (B, S, DM)
    float* score = out + (size_t)NT * DM;       // (B, H, S, 257)

    float *q, *k, *v, *attn, *h, *ff;
    cudaGetSymbolAddress((void**)&q,    g_q);
    cudaGetSymbolAddress((void**)&k,    g_k);
    cudaGetSymbolAddress((void**)&v,    g_v);
    cudaGetSymbolAddress((void**)&attn, g_attn);
    cudaGetSymbolAddress((void**)&h,    g_h);
    cudaGetSymbolAddress((void**)&ff,   g_ff);

    const size_t attn_smem = (size_t)KW * KPAD * sizeof(float);  // 133120 B
    cudaFuncSetAttribute(attn_scores_kernel,
                         cudaFuncAttributeMaxDynamicSharedMemorySize, attn_smem);
    cudaFuncSetAttribute(attn_pv_kernel,
                         cudaFuncAttributeMaxDynamicSharedMemorySize, attn_smem);

    // QKV projections (head-split layout, q pre-scaled by 1/sqrt(D))
    dim3 gqkv(DM / 128, NT / 128);
    tgemm_kernel<2><<<gqkv, 256>>>(x, Wq, bq, q, DM, DM, 0.125f);
    tgemm_kernel<2><<<gqkv, 256>>>(x, Wk, bk, k, DM, DM, 1.0f);
    tgemm_kernel<2><<<gqkv, 256>>>(x, Wv, bv, v, DM, DM, 1.0f);

    // sliding-window attention
    dim3 gattn(S_ / QC, B_ * H_);
    attn_scores_kernel<<<gattn, 256, attn_smem>>>(q, k, score);
    attn_pv_kernel<<<gattn, 256, attn_smem>>>(v, score, attn);

    // h = LN1(attn + x)
    ln_kernel<<<NT, 128>>>(attn, x, ln1g, ln1b, h);

    // FFN
    dim3 gf1(DH / 128, NT / 128);
    tgemm_kernel<1><<<gf1, 256>>>(h, Wf1, bf1, ff, DH, DM, 1.0f);
    dim3 gf2(DM / 128, NT / 128);
    tgemm_kernel<0><<<gf2, 256>>>(ff, Wf2, bf2, attn, DM, DH, 1.0f);  // reuse attn buf

    // out = LN2(ff2 + h)
    ln_kernel<<<NT, 128>>>(attn, h, ln2g, ln2b, out);
}